// round 6
// baseline (speedup 1.0000x reference)
#include <cuda_runtime.h>
#include <cstdint>

#define NATOMS_V 100
#define DIM    200      // feature dim / K
#define NPAD   256      // padded col dim
#define LHID   6
#define LPRED  3
#define NADD   4
#define DPRED  204
#define BMOL   256
#define NA     32
#define NTOT   8192
#define CK     8        // GEMM k-chunk
#define NCHUNK (DIM / CK)   // 25
#define NSTR   208

typedef unsigned long long ull;

// ---------------- device scratch (static, no allocations) ----------------
__device__ float g_avtd[2][DIM][2 * NTOT];   // dup-transposed activations, ping-pong (26.2 MB)
__device__ float g_hv[NTOT][NPAD];           // GEMM output, normal layout      (8.4 MB)
__device__ float g_wpad[9][DIM][NPAD];       // padded weights                   (1.8 MB)
__device__ float g_bpad[9][NPAD];            // padded biases

// ---------------- helpers ----------------
__device__ __forceinline__ void ffma2(ull& d, ull a, ull b) {
    asm("fma.rn.f32x2 %0, %1, %2, %0;" : "+l"(d) : "l"(a), "l"(b));
}
__device__ __forceinline__ uint32_t smaddr(const void* p) {
    return (uint32_t)__cvta_generic_to_shared(p);
}
__device__ __forceinline__ void cp_async16(uint32_t saddr, const void* g) {
    asm volatile("cp.async.cg.shared.global [%0], [%1], 16;" :: "r"(saddr), "l"(g));
}
__device__ __forceinline__ void cp_commit() {
    asm volatile("cp.async.commit_group;" ::: "memory");
}
__device__ __forceinline__ void cp_wait0() {
    asm volatile("cp.async.wait_group 0;" ::: "memory");
}

// ---------------- prep: pad weights/biases into scratch ----------------
__global__ void prep_kernel(const float* __restrict__ Waw, const float* __restrict__ Wab,
                            const float* __restrict__ Wow, const float* __restrict__ Wob)
{
    const int stride = gridDim.x * blockDim.x;
    for (int idx = blockIdx.x * blockDim.x + threadIdx.x; idx < 9 * DIM * NPAD; idx += stride) {
        const int l = idx / (DIM * NPAD);
        const int rem = idx - l * DIM * NPAD;
        const int k = rem >> 8, c = rem & 255;
        float v = 0.f;
        if (c < DIM)
            v = (l < LHID) ? Waw[(l * DIM + k) * DIM + c]
                           : Wow[((l - LHID) * DIM + k) * DIM + c];
        g_wpad[l][k][c] = v;
    }
    for (int idx = blockIdx.x * blockDim.x + threadIdx.x; idx < 9 * NPAD; idx += stride) {
        const int l = idx >> 8, c = idx & 255;
        float v = 0.f;
        if (c < DIM)
            v = (l < LHID) ? Wab[l * DIM + c] : Wob[(l - LHID) * DIM + c];
        g_bpad[l][c] = v;
    }
}

// ---------------- embed: avtd[0][k][2r] = embed[atoms[r]][k] ----------------
__global__ void embed_kernel(const int* __restrict__ atoms,
                             const float* __restrict__ embed_atom)
{
    int idx = blockIdx.x * blockDim.x + threadIdx.x;   // over DIM * NTOT
    if (idx >= DIM * NTOT) return;
    const int k = idx >> 13;          // / 8192
    const int r = idx & (NTOT - 1);
    const float v = embed_atom[atoms[r] * DIM + k];
    *(float2*)&g_avtd[0][k][2 * r] = make_float2(v, v);
}

// ---------------- GEMM: C = relu(A @ W_l + b_l) ----------------
// grid (128, 2): 64-row x 128-col tiles. 256 threads = 8 warps.
// warp owns 8-row oct; lane owns col pairs (2*lane, 2*lane+1) and (+64).
// WMODE 0: write g_hv normal.  WMODE 1: write g_avtd[pout] dup-transposed.
template<int WMODE>
__global__ __launch_bounds__(256) void gemm_kernel(int l, int pin, int pout)
{
    __shared__ float sA[2][CK][128];   // dup rows for 64 rows
    __shared__ float sW[2][CK][128];

    const int tid = threadIdx.x;
    const int warp = tid >> 5, lane = tid & 31;
    const int row0 = blockIdx.x * 64;
    const int coff = blockIdx.y * 128;
    const int kk_c = tid >> 5;
    const int sg4  = (tid & 31) * 4;

    ull acc[8][2];
    #pragma unroll
    for (int r = 0; r < 8; r++) { acc[r][0] = 0ull; acc[r][1] = 0ull; }

    // prologue: chunk 0
    cp_async16(smaddr(&sA[0][kk_c][sg4]), &g_avtd[pin][kk_c][2 * row0 + sg4]);
    cp_async16(smaddr(&sW[0][kk_c][sg4]), &g_wpad[l][kk_c][coff + sg4]);
    cp_commit();

    for (int nc = 0; nc < NCHUNK; nc++) {
        cp_wait0();
        __syncthreads();
        if (nc + 1 < NCHUNK) {
            const int k0 = (nc + 1) * CK, bnx = (nc + 1) & 1;
            cp_async16(smaddr(&sA[bnx][kk_c][sg4]), &g_avtd[pin][k0 + kk_c][2 * row0 + sg4]);
            cp_async16(smaddr(&sW[bnx][kk_c][sg4]), &g_wpad[l][k0 + kk_c][coff + sg4]);
        }
        cp_commit();
        const int b = nc & 1;
        #pragma unroll
        for (int kk = 0; kk < CK; kk++) {
            ulonglong2 a0 = *(const ulonglong2*)&sA[b][kk][warp * 16 + 0];   // rows 0,1 (dup)
            ulonglong2 a1 = *(const ulonglong2*)&sA[b][kk][warp * 16 + 4];   // rows 2,3
            ulonglong2 a2 = *(const ulonglong2*)&sA[b][kk][warp * 16 + 8];   // rows 4,5
            ulonglong2 a3 = *(const ulonglong2*)&sA[b][kk][warp * 16 + 12];  // rows 6,7
            ull w0 = *(const ull*)&sW[b][kk][2 * lane];
            ull w1 = *(const ull*)&sW[b][kk][2 * lane + 64];
            ffma2(acc[0][0], a0.x, w0); ffma2(acc[0][1], a0.x, w1);
            ffma2(acc[1][0], a0.y, w0); ffma2(acc[1][1], a0.y, w1);
            ffma2(acc[2][0], a1.x, w0); ffma2(acc[2][1], a1.x, w1);
            ffma2(acc[3][0], a1.y, w0); ffma2(acc[3][1], a1.y, w1);
            ffma2(acc[4][0], a2.x, w0); ffma2(acc[4][1], a2.x, w1);
            ffma2(acc[5][0], a2.y, w0); ffma2(acc[5][1], a2.y, w1);
            ffma2(acc[6][0], a3.x, w0); ffma2(acc[6][1], a3.x, w1);
            ffma2(acc[7][0], a3.y, w0); ffma2(acc[7][1], a3.y, w1);
        }
    }

    const float2 b0 = *(const float2*)&g_bpad[l][coff + 2 * lane];
    const float2 b1 = *(const float2*)&g_bpad[l][coff + 2 * lane + 64];
    const int c0 = coff + 2 * lane;
    const int c1 = c0 + 64;
    #pragma unroll
    for (int r = 0; r < 8; r++) {
        const int grow = row0 + warp * 8 + r;
        float2 v0 = *(float2*)&acc[r][0];
        float2 v1 = *(float2*)&acc[r][1];
        v0.x = fmaxf(v0.x + b0.x, 0.f); v0.y = fmaxf(v0.y + b0.y, 0.f);
        v1.x = fmaxf(v1.x + b1.x, 0.f); v1.y = fmaxf(v1.y + b1.y, 0.f);
        if (WMODE == 0) {
            *(float2*)&g_hv[grow][c0] = v0;
            *(float2*)&g_hv[grow][c1] = v1;
        } else {
            if (c0 < DIM)     *(float2*)&g_avtd[pout][c0][2 * grow]     = make_float2(v0.x, v0.x);
            if (c0 + 1 < DIM) *(float2*)&g_avtd[pout][c0 + 1][2 * grow] = make_float2(v0.y, v0.y);
            if (c1 < DIM)     *(float2*)&g_avtd[pout][c1][2 * grow]     = make_float2(v1.x, v1.x);
            if (c1 + 1 < DIM) *(float2*)&g_avtd[pout][c1 + 1][2 * grow] = make_float2(v1.y, v1.y);
        }
    }
}

// ---------------- mix: av = normalize(hv + M @ hv) per molecule ----------------
__global__ __launch_bounds__(256) void mix_kernel(int l, int pout,
                                                  const int* __restrict__ atoms,
                                                  const float* __restrict__ dist,
                                                  const float* __restrict__ gamma_tab)
{
    __shared__ float  sHV[NA][NSTR];   // 26.6 KB
    __shared__ float2 sMd[NA][NA];     // 8 KB (dup)
    __shared__ float  sGam[NA];
    __shared__ int    sAt[NA];

    const int m = blockIdx.x;
    const int base = m * NA;
    const int tid = threadIdx.x;
    const int warp = tid >> 5, lane = tid & 31;

    if (tid < NA) sAt[tid] = atoms[base + tid];
    __syncthreads();
    if (tid < NA) sGam[tid] = gamma_tab[l * NATOMS_V + sAt[tid]];
    // load hv rows (coalesced): warp w rows 4w..4w+3
    #pragma unroll
    for (int rr = 0; rr < 4; rr++) {
        const int r = warp * 4 + rr;
        for (int c = lane; c < DIM; c += 32)
            sHV[r][c] = g_hv[base + r][c];
    }
    __syncthreads();
    for (int idx = tid; idx < NA * NA; idx += 256) {
        const int i = idx >> 5, j = idx & 31;
        const float d = dist[(base + i) * NTOT + base + j];
        const float e = __expf(-sGam[j] * d * d);
        sMd[i][j] = make_float2(e, e);
    }
    __syncthreads();

    // mix: 8 warps x 4 rows, full 200 cols per warp
    const int i0 = warp * 4;
    const bool has3 = (lane < 4);
    const int co0 = 2 * lane, co1 = co0 + 64, co2 = co0 + 128, co3 = 192 + 2 * lane;

    ull acc[4][4];
    #pragma unroll
    for (int r = 0; r < 4; r++) {
        acc[r][0] = *(const ull*)&sHV[i0 + r][co0];
        acc[r][1] = *(const ull*)&sHV[i0 + r][co1];
        acc[r][2] = *(const ull*)&sHV[i0 + r][co2];
        acc[r][3] = has3 ? *(const ull*)&sHV[i0 + r][co3] : 0ull;
    }
    #pragma unroll 4
    for (int j = 0; j < NA; j++) {
        ull mm[4];
        #pragma unroll
        for (int r = 0; r < 4; r++) mm[r] = *(const ull*)&sMd[i0 + r][j];
        ull h0 = *(const ull*)&sHV[j][co0];
        ull h1 = *(const ull*)&sHV[j][co1];
        ull h2 = *(const ull*)&sHV[j][co2];
        #pragma unroll
        for (int r = 0; r < 4; r++) {
            ffma2(acc[r][0], mm[r], h0);
            ffma2(acc[r][1], mm[r], h1);
            ffma2(acc[r][2], mm[r], h2);
        }
        if (has3) {
            ull h3 = *(const ull*)&sHV[j][co3];
            #pragma unroll
            for (int r = 0; r < 4; r++) ffma2(acc[r][3], mm[r], h3);
        }
    }
    #pragma unroll
    for (int r = 0; r < 4; r++) {
        float ss = 0.f;
        #pragma unroll
        for (int u = 0; u < 4; u++) {
            float2 v = *(float2*)&acc[r][u];
            ss += v.x * v.x + v.y * v.y;
        }
        #pragma unroll
        for (int o = 16; o > 0; o >>= 1)
            ss += __shfl_xor_sync(0xffffffffu, ss, o);
        const float scale = 1.f / fmaxf(sqrtf(ss), 1e-12f);
        const int R2 = 2 * (base + i0 + r);
        #pragma unroll
        for (int u = 0; u < 3; u++) {
            const int c = co0 + 64 * u;
            float2 v = *(float2*)&acc[r][u];
            *(float2*)&g_avtd[pout][c][R2]     = make_float2(v.x * scale, v.x * scale);
            *(float2*)&g_avtd[pout][c + 1][R2] = make_float2(v.y * scale, v.y * scale);
        }
        if (has3) {
            float2 v = *(float2*)&acc[r][3];
            *(float2*)&g_avtd[pout][co3][R2]     = make_float2(v.x * scale, v.x * scale);
            *(float2*)&g_avtd[pout][co3 + 1][R2] = make_float2(v.y * scale, v.y * scale);
        }
    }
}

// ---------------- tail: row-sum + pred MLP + final dot ----------------
__global__ __launch_bounds__(256) void tail_kernel(const float* __restrict__ adducts,
                                                   const float* __restrict__ W_pred_w,
                                                   const float* __restrict__ W_pred_b,
                                                   const float* __restrict__ W_prop_w,
                                                   const float* __restrict__ W_prop_b,
                                                   float* __restrict__ out)
{
    __shared__ float pv[2][DPRED + 4];
    __shared__ float red[8];
    const int m = blockIdx.x;
    const int tid = threadIdx.x;

    if (tid < DIM) {
        float s = 0.f;
        #pragma unroll 8
        for (int i = 0; i < NA; i++) s += g_hv[m * NA + i][tid];
        pv[0][tid] = s;
    } else if (tid < DPRED) {
        pv[0][tid] = adducts[m * NADD + (tid - DIM)];
    }
    __syncthreads();

    int cur = 0;
    for (int l = 0; l < LPRED; l++) {
        if (tid < DPRED) {
            const float* Wp = W_pred_w + l * DPRED * DPRED;
            float acc = W_pred_b[l * DPRED + tid];
            #pragma unroll 4
            for (int k = 0; k < DPRED; k++)
                acc += pv[cur][k] * Wp[k * DPRED + tid];
            pv[cur ^ 1][tid] = fmaxf(acc, 0.f);
        }
        __syncthreads();
        cur ^= 1;
    }

    float p = (tid < DPRED) ? pv[cur][tid] * W_prop_w[tid] : 0.f;
    #pragma unroll
    for (int o = 16; o > 0; o >>= 1)
        p += __shfl_xor_sync(0xffffffffu, p, o);
    if ((tid & 31) == 0) red[tid >> 5] = p;
    __syncthreads();
    if (tid == 0) {
        float s = 0.f;
        #pragma unroll
        for (int w = 0; w < 8; w++) s += red[w];
        out[m] = s + W_prop_b[0];
    }
}

// ---------------- launch ----------------
extern "C" void kernel_launch(void* const* d_in, const int* in_sizes, int n_in,
                              void* d_out, int out_size)
{
    const int*   atoms      = (const int*)  d_in[0];
    const float* dist       = (const float*)d_in[1];
    const float* adducts    = (const float*)d_in[2];
    const float* embed_atom = (const float*)d_in[3];
    const float* gamma_tab  = (const float*)d_in[4];
    const float* W_atom_w   = (const float*)d_in[5];
    const float* W_atom_b   = (const float*)d_in[6];
    const float* W_out_w    = (const float*)d_in[7];
    const float* W_out_b    = (const float*)d_in[8];
    const float* W_pred_w   = (const float*)d_in[9];
    const float* W_pred_b   = (const float*)d_in[10];
    const float* W_prop_w   = (const float*)d_in[11];
    const float* W_prop_b   = (const float*)d_in[12];
    float* out = (float*)d_out;

    prep_kernel<<<512, 256>>>(W_atom_w, W_atom_b, W_out_w, W_out_b);
    embed_kernel<<<(DIM * NTOT + 255) / 256, 256>>>(atoms, embed_atom);

    dim3 ggrid(NTOT / 64, NPAD / 128);   // (128, 2)
    for (int l = 0; l < LHID; l++) {
        const int pin = l & 1;
        gemm_kernel<0><<<ggrid, 256>>>(l, pin, 0);
        mix_kernel<<<BMOL, 256>>>(l, pin ^ 1, atoms, dist, gamma_tab);
    }
    // out layers: widx 6,7 write avtd; widx 8 writes hv
    gemm_kernel<1><<<ggrid, 256>>>(6, 0, 1);
    gemm_kernel<1><<<ggrid, 256>>>(7, 1, 0);
    gemm_kernel<0><<<ggrid, 256>>>(8, 0, 0);

    tail_kernel<<<BMOL, 256>>>(adducts, W_pred_w, W_pred_b, W_prop_w, W_prop_b, out);
}

// round 7
// speedup vs baseline: 1.5410x; 1.5410x over previous
#include <cuda_runtime.h>
#include <cstdint>

#define NATOMS_V 100
#define DIM    200
#define NPAD   256
#define LHID   6
#define LPRED  3
#define NADD   4
#define DPRED  204
#define NA     32
#define NTOT   8192
#define NSTR   208

typedef unsigned long long ull;

// ---------- device scratch (static, no allocations) ----------
__device__ float g_act[2][NTOT][NPAD];     // activations ping-pong, normal layout (16.8 MB)
__device__ float g_wpad[9][DIM][NPAD];     // padded weights
__device__ float g_bpad[9][NPAD];          // padded biases

// ---------- helpers ----------
__device__ __forceinline__ void ffma2(ull& d, ull a, ull b) {
    asm("fma.rn.f32x2 %0, %1, %2, %0;" : "+l"(d) : "l"(a), "l"(b));
}
__device__ __forceinline__ ull dupf(float v) {
    float2 t = make_float2(v, v);
    return *(ull*)&t;
}
__device__ __forceinline__ uint32_t smaddr(const void* p) {
    return (uint32_t)__cvta_generic_to_shared(p);
}
__device__ __forceinline__ void cp_async16(uint32_t s, const void* g) {
    asm volatile("cp.async.cg.shared.global [%0], [%1], 16;" :: "r"(s), "l"(g));
}
__device__ __forceinline__ void cp_commit() { asm volatile("cp.async.commit_group;" ::: "memory"); }
__device__ __forceinline__ void cp_wait0()  { asm volatile("cp.async.wait_group 0;" ::: "memory"); }

struct LayerSmem {
    float  sA[2][64][36];       // A chunk ring: 64 rows x 32 k      (18.4 KB)
    float  sW[2][32][264];      // W chunk ring: 32 k x 256 cols     (67.6 KB)
    float  sHV[64][NSTR];       // GEMM output for epilogue          (53.2 KB)
    float2 sMd[2][NA][NA];      // message matrices, dup             (16.4 KB)
    float  sGam[64];
    float  spv[2][2][DPRED + 4];
    float  sred[2][8];
};   // ~159.7 KB, 1 CTA/SM

// ---------- prep: pad W/b ----------
__global__ void prep_kernel(const float* __restrict__ Waw, const float* __restrict__ Wab,
                            const float* __restrict__ Wow, const float* __restrict__ Wob)
{
    const int stride = gridDim.x * blockDim.x;
    for (int idx = blockIdx.x * blockDim.x + threadIdx.x; idx < 9 * DIM * NPAD; idx += stride) {
        const int l = idx / (DIM * NPAD);
        const int rem = idx - l * DIM * NPAD;
        const int k = rem >> 8, c = rem & 255;
        float v = 0.f;
        if (c < DIM)
            v = (l < LHID) ? Waw[(l * DIM + k) * DIM + c]
                           : Wow[((l - LHID) * DIM + k) * DIM + c];
        g_wpad[l][k][c] = v;
    }
    for (int idx = blockIdx.x * blockDim.x + threadIdx.x; idx < 9 * NPAD; idx += stride) {
        const int l = idx >> 8, c = idx & 255;
        float v = 0.f;
        if (c < DIM)
            v = (l < LHID) ? Wab[l * DIM + c] : Wob[(l - LHID) * DIM + c];
        g_bpad[l][c] = v;
    }
}

// ---------- embed: g_act[0][row][c] = embed[atoms[row]][c] ----------
__global__ void embed_kernel(const int* __restrict__ atoms,
                             const float* __restrict__ embed_atom)
{
    int idx = blockIdx.x * blockDim.x + threadIdx.x;
    if (idx >= NTOT * DIM) return;
    const int row = idx / DIM, c = idx - row * DIM;
    g_act[0][row][c] = embed_atom[atoms[row] * DIM + c];
}

// ---------- layer kernel: GEMM(64x256 tile) + fused epilogue ----------
// MODE 0: hidden layer  -> relu, mix, normalize, write g_act[pout]
// MODE 1: out layer     -> relu, write g_act[pout]
// MODE 2: final layer   -> relu, molecule sum + pred MLP + output
template<int MODE>
__global__ __launch_bounds__(512, 1)
void layer_kernel(int l, int pin, int pout,
                  const int*   __restrict__ atoms,
                  const float* __restrict__ dist,
                  const float* __restrict__ gamma_tab,
                  const float* __restrict__ adducts,
                  const float* __restrict__ W_pred_w,
                  const float* __restrict__ W_pred_b,
                  const float* __restrict__ W_prop_w,
                  const float* __restrict__ W_prop_b,
                  float* __restrict__ out)
{
    extern __shared__ char smraw[];
    LayerSmem& sm = *reinterpret_cast<LayerSmem*>(smraw);

    const int tid  = threadIdx.x;
    const int warp = tid >> 5, lane = tid & 31;
    const int row0 = blockIdx.x * 64;
    const int rg = warp >> 1, cg = warp & 1;    // 8 row-groups x 2 col-groups
    const int r0 = rg * 8;
    const int c0 = cg * 128 + 2 * lane;
    const int c1 = c0 + 64;
    const bool v1 = (cg == 0) || (lane < 4);    // c1 < 200 ?

    // stage A/W chunk c into ring slot buf. chunks: 6 x 32k + 1 x 8k
    auto stage = [&](int c, int buf) {
        const int k0 = c * 32;
        if (c < 6) {
            const int row = tid >> 3, q = (tid & 7) * 4;
            cp_async16(smaddr(&sm.sA[buf][row][q]), &g_act[pin][row0 + row][k0 + q]);
            #pragma unroll
            for (int i = 0; i < 4; i++) {
                const int idx = tid + i * 512;
                const int kr = idx >> 6, c4 = (idx & 63) * 4;
                cp_async16(smaddr(&sm.sW[buf][kr][c4]), &g_wpad[l][k0 + kr][c4]);
            }
        } else {
            if (tid < 128) {
                const int row = tid >> 1, q = (tid & 1) * 4;
                cp_async16(smaddr(&sm.sA[buf][row][q]), &g_act[pin][row0 + row][k0 + q]);
            }
            const int kr = tid >> 6, c4 = (tid & 63) * 4;
            if (kr < 8)
                cp_async16(smaddr(&sm.sW[buf][kr][c4]), &g_wpad[l][k0 + kr][c4]);
        }
    };

    stage(0, 0);
    cp_commit();

    if (MODE == 0) {   // mix prep: gamma + message matrices (overlaps stage 0)
        if (tid < 64) sm.sGam[tid] = gamma_tab[l * NATOMS_V + atoms[row0 + tid]];
        __syncthreads();
        #pragma unroll
        for (int i = 0; i < 4; i++) {
            const int idx = tid + i * 512;
            const int mol = idx >> 10, ii = (idx >> 5) & 31, jj = idx & 31;
            const float d = dist[(row0 + mol * 32 + ii) * NTOT + row0 + mol * 32 + jj];
            const float e = __expf(-sm.sGam[mol * 32 + jj] * d * d);
            sm.sMd[mol][ii][jj] = make_float2(e, e);
        }
    }

    ull acc[8][2];
    #pragma unroll
    for (int r = 0; r < 8; r++) { acc[r][0] = 0ull; acc[r][1] = 0ull; }

    for (int c = 0; c < 7; c++) {
        cp_wait0();
        __syncthreads();
        if (c + 1 < 7) stage(c + 1, (c + 1) & 1);
        cp_commit();
        const int buf = c & 1;
        const int cs = (c < 6) ? 32 : 8;
        for (int kk = 0; kk < cs; kk += 4) {
            float4 a4[8];
            #pragma unroll
            for (int r = 0; r < 8; r++)
                a4[r] = *(const float4*)&sm.sA[buf][r0 + r][kk];   // broadcast LDS.128, 4 k's
            #pragma unroll
            for (int q = 0; q < 4; q++) {
                ull w0 = *(const ull*)&sm.sW[buf][kk + q][c0];
                ull w1 = *(const ull*)&sm.sW[buf][kk + q][c1];
                #pragma unroll
                for (int r = 0; r < 8; r++) {
                    const float av = ((const float*)&a4[r])[q];
                    const ull a = dupf(av);
                    ffma2(acc[r][0], a, w0);
                    ffma2(acc[r][1], a, w1);
                }
            }
        }
    }

    const float2 b0 = *(const float2*)&g_bpad[l][c0];
    const float2 b1 = *(const float2*)&g_bpad[l][c1];

    if (MODE == 1) {   // plain relu layer: direct global store
        #pragma unroll
        for (int r = 0; r < 8; r++) {
            const int grow = row0 + r0 + r;
            float2 v = *(float2*)&acc[r][0];
            *(float2*)&g_act[pout][grow][c0] =
                make_float2(fmaxf(v.x + b0.x, 0.f), fmaxf(v.y + b0.y, 0.f));
            if (v1) {
                float2 u = *(float2*)&acc[r][1];
                *(float2*)&g_act[pout][grow][c1] =
                    make_float2(fmaxf(u.x + b1.x, 0.f), fmaxf(u.y + b1.y, 0.f));
            }
        }
        return;
    }

    // MODE 0 / 2: hv -> smem for epilogue
    #pragma unroll
    for (int r = 0; r < 8; r++) {
        float2 v = *(float2*)&acc[r][0];
        *(float2*)&sm.sHV[r0 + r][c0] =
            make_float2(fmaxf(v.x + b0.x, 0.f), fmaxf(v.y + b0.y, 0.f));
        if (v1) {
            float2 u = *(float2*)&acc[r][1];
            *(float2*)&sm.sHV[r0 + r][c1] =
                make_float2(fmaxf(u.x + b1.x, 0.f), fmaxf(u.y + b1.y, 0.f));
        }
    }
    __syncthreads();

    if (MODE == 0) {
        // mix + normalize: warp -> (mol = warp>>3, 4 rows), full 200 cols
        const int mol = warp >> 3;
        const int i0 = (warp & 7) * 4;
        const bool has3 = (lane < 4);
        const int m0c = 2 * lane, m1c = m0c + 64, m2c = m0c + 128, m3c = 192 + 2 * lane;
        const float (*hv)[NSTR] = (const float (*)[NSTR])&sm.sHV[mol * 32];

        ull a2[4][4];
        #pragma unroll
        for (int r = 0; r < 4; r++) {
            a2[r][0] = *(const ull*)&hv[i0 + r][m0c];
            a2[r][1] = *(const ull*)&hv[i0 + r][m1c];
            a2[r][2] = *(const ull*)&hv[i0 + r][m2c];
            a2[r][3] = has3 ? *(const ull*)&hv[i0 + r][m3c] : 0ull;
        }
        #pragma unroll 4
        for (int j = 0; j < NA; j++) {
            ull mm[4];
            #pragma unroll
            for (int r = 0; r < 4; r++) mm[r] = *(const ull*)&sm.sMd[mol][i0 + r][j];
            ull h0 = *(const ull*)&hv[j][m0c];
            ull h1 = *(const ull*)&hv[j][m1c];
            ull h2 = *(const ull*)&hv[j][m2c];
            #pragma unroll
            for (int r = 0; r < 4; r++) {
                ffma2(a2[r][0], mm[r], h0);
                ffma2(a2[r][1], mm[r], h1);
                ffma2(a2[r][2], mm[r], h2);
            }
            if (has3) {
                ull h3 = *(const ull*)&hv[j][m3c];
                #pragma unroll
                for (int r = 0; r < 4; r++) ffma2(a2[r][3], mm[r], h3);
            }
        }
        #pragma unroll
        for (int r = 0; r < 4; r++) {
            float ss = 0.f;
            #pragma unroll
            for (int u = 0; u < 4; u++) {
                float2 v = *(float2*)&a2[r][u];
                ss += v.x * v.x + v.y * v.y;
            }
            #pragma unroll
            for (int o = 16; o > 0; o >>= 1)
                ss += __shfl_xor_sync(0xffffffffu, ss, o);
            const float scale = 1.f / fmaxf(sqrtf(ss), 1e-12f);
            const int grow = row0 + mol * 32 + i0 + r;
            #pragma unroll
            for (int u = 0; u < 3; u++) {
                float2 v = *(float2*)&a2[r][u];
                *(float2*)&g_act[pout][grow][m0c + 64 * u] =
                    make_float2(v.x * scale, v.y * scale);
            }
            if (has3) {
                float2 v = *(float2*)&a2[r][3];
                *(float2*)&g_act[pout][grow][m3c] =
                    make_float2(v.x * scale, v.y * scale);
            }
        }
        return;
    }

    // MODE 2: molecule sum + adducts + pred MLP + final dot (2 molecules per CTA)
    {
        const int mol = tid >> 8;          // 0/1 : 256 threads each
        const int col = tid & 255;
        if (col < DPRED) {
            float s;
            if (col < DIM) {
                s = 0.f;
                #pragma unroll 8
                for (int i = 0; i < NA; i++) s += sm.sHV[mol * 32 + i][col];
            } else {
                s = adducts[(2 * blockIdx.x + mol) * NADD + (col - DIM)];
            }
            sm.spv[0][mol][col] = s;
        }
        __syncthreads();

        int cur = 0;
        for (int lp = 0; lp < LPRED; lp++) {
            if (col < DPRED) {
                const float* Wp = W_pred_w + lp * DPRED * DPRED;
                float a = W_pred_b[lp * DPRED + col];
                #pragma unroll 4
                for (int k = 0; k < DPRED; k++)
                    a += sm.spv[cur][mol][k] * Wp[k * DPRED + col];
                sm.spv[cur ^ 1][mol][col] = fmaxf(a, 0.f);
            }
            __syncthreads();
            cur ^= 1;
        }

        float p = (col < DPRED) ? sm.spv[cur][mol][col] * W_prop_w[col] : 0.f;
        #pragma unroll
        for (int o = 16; o > 0; o >>= 1)
            p += __shfl_xor_sync(0xffffffffu, p, o);
        if (lane == 0) sm.sred[mol][warp & 7] = p;
        __syncthreads();
        if ((tid & 255) == 0) {
            float s = 0.f;
            #pragma unroll
            for (int w = 0; w < 8; w++) s += sm.sred[mol][w];
            out[2 * blockIdx.x + mol] = s + W_prop_b[0];
        }
    }
}

// ---------- launch ----------
extern "C" void kernel_launch(void* const* d_in, const int* in_sizes, int n_in,
                              void* d_out, int out_size)
{
    const int*   atoms      = (const int*)  d_in[0];
    const float* dist       = (const float*)d_in[1];
    const float* adducts    = (const float*)d_in[2];
    const float* embed_atom = (const float*)d_in[3];
    const float* gamma_tab  = (const float*)d_in[4];
    const float* W_atom_w   = (const float*)d_in[5];
    const float* W_atom_b   = (const float*)d_in[6];
    const float* W_out_w    = (const float*)d_in[7];
    const float* W_out_b    = (const float*)d_in[8];
    const float* W_pred_w   = (const float*)d_in[9];
    const float* W_pred_b   = (const float*)d_in[10];
    const float* W_prop_w   = (const float*)d_in[11];
    const float* W_prop_b   = (const float*)d_in[12];
    float* out = (float*)d_out;

    const int smem = (int)sizeof(LayerSmem);
    cudaFuncSetAttribute(layer_kernel<0>, cudaFuncAttributeMaxDynamicSharedMemorySize, smem);
    cudaFuncSetAttribute(layer_kernel<1>, cudaFuncAttributeMaxDynamicSharedMemorySize, smem);
    cudaFuncSetAttribute(layer_kernel<2>, cudaFuncAttributeMaxDynamicSharedMemorySize, smem);

    prep_kernel<<<512, 256>>>(W_atom_w, W_atom_b, W_out_w, W_out_b);
    embed_kernel<<<(NTOT * DIM + 511) / 512, 512>>>(atoms, embed_atom);

    for (int l = 0; l < LHID; l++)
        layer_kernel<0><<<128, 512, smem>>>(l, l & 1, (l & 1) ^ 1,
            atoms, dist, gamma_tab, adducts, W_pred_w, W_pred_b, W_prop_w, W_prop_b, out);

    layer_kernel<1><<<128, 512, smem>>>(6, 0, 1,
        atoms, dist, gamma_tab, adducts, W_pred_w, W_pred_b, W_prop_w, W_prop_b, out);
    layer_kernel<1><<<128, 512, smem>>>(7, 1, 0,
        atoms, dist, gamma_tab, adducts, W_pred_w, W_pred_b, W_prop_w, W_prop_b, out);
    layer_kernel<2><<<128, 512, smem>>>(8, 0, 0,
        atoms, dist, gamma_tab, adducts, W_pred_w, W_pred_b, W_prop_w, W_prop_b, out);
}